// round 7
// baseline (speedup 1.0000x reference)
#include <cuda_runtime.h>

// TensorProductUniform3x1d:
//   B=100000, NSEG=4, U=128, NPATH=20
//   out[b, i2, :] += c[p] * x0[b, i0[p], :] * x1[b, i1[p], :]
//
// Fused kernel: per-block build of collapsed 4x4x4 coefficient tensor W in
// shared, then static fully-unrolled contraction.
//
// R7: keep 128-bit accesses (R6 showed narrower loads regress), double
// per-warp MLP by processing TWO rows per warp: 16 front-batched float4
// loads per thread. Warp still covers 512B contiguous per segment.

#define NSEG 4
#define U 128
#define NPATH 20

__global__ __launch_bounds__(256)
void tp_uniform_fused_kernel(const float4* __restrict__ x0,
                             const float4* __restrict__ x1,
                             const float*  __restrict__ coeff,
                             const int*    __restrict__ idx,
                             float4* __restrict__ out,
                             int nrows) {
    __shared__ float sW[NSEG * NSEG * NSEG];

    // Build W[i2][i0][i1] = sum_p coeff[p] * [idx[p]==(i0,i1,i2)]
    int t = threadIdx.x;
    if (t < NSEG * NSEG * NSEG) {
        int i2 = t >> 4;
        int i0 = (t >> 2) & 3;
        int i1 = t & 3;
        float w = 0.0f;
        #pragma unroll
        for (int p = 0; p < NPATH; p++) {
            int p0 = __ldg(&idx[3 * p + 0]);
            int p1 = __ldg(&idx[3 * p + 1]);
            int p2 = __ldg(&idx[3 * p + 2]);
            if (p0 == i0 && p1 == i1 && p2 == i2) w += __ldg(&coeff[p]);
        }
        sW[t] = w;
    }
    __syncthreads();

    int gid   = blockIdx.x * blockDim.x + threadIdx.x;
    int pair  = gid >> 5;              // warp index = row pair
    int lane  = gid & 31;
    int row0  = pair * 2;
    if (row0 >= nrows) return;
    bool has2 = (row0 + 1) < nrows;

    const int RS = NSEG * U / 4;       // 128 float4 per row
    size_t base0 = (size_t)row0 * RS + lane;
    size_t base1 = base0 + (has2 ? RS : 0);   // alias row0 if odd tail (harmless reload)

    // Front-batch 16 loads (2 rows x 2 arrays x 4 segments), all 128-bit.
    float4 a0[NSEG], b0[NSEG], a1[NSEG], b1[NSEG];
    #pragma unroll
    for (int s = 0; s < NSEG; s++) a0[s] = __ldg(&x0[base0 + s * (U / 4)]);
    #pragma unroll
    for (int s = 0; s < NSEG; s++) b0[s] = __ldg(&x1[base0 + s * (U / 4)]);
    #pragma unroll
    for (int s = 0; s < NSEG; s++) a1[s] = __ldg(&x0[base1 + s * (U / 4)]);
    #pragma unroll
    for (int s = 0; s < NSEG; s++) b1[s] = __ldg(&x1[base1 + s * (U / 4)]);

    #pragma unroll
    for (int i2 = 0; i2 < NSEG; i2++) {
        float4 acc0 = make_float4(0.f, 0.f, 0.f, 0.f);
        float4 acc1 = make_float4(0.f, 0.f, 0.f, 0.f);
        #pragma unroll
        for (int i0 = 0; i0 < NSEG; i0++) {
            float4 t0 = make_float4(0.f, 0.f, 0.f, 0.f);
            float4 t1 = make_float4(0.f, 0.f, 0.f, 0.f);
            #pragma unroll
            for (int i1 = 0; i1 < NSEG; i1++) {
                float w = sW[(i2 * NSEG + i0) * NSEG + i1];
                t0.x = fmaf(w, b0[i1].x, t0.x);
                t0.y = fmaf(w, b0[i1].y, t0.y);
                t0.z = fmaf(w, b0[i1].z, t0.z);
                t0.w = fmaf(w, b0[i1].w, t0.w);
                t1.x = fmaf(w, b1[i1].x, t1.x);
                t1.y = fmaf(w, b1[i1].y, t1.y);
                t1.z = fmaf(w, b1[i1].z, t1.z);
                t1.w = fmaf(w, b1[i1].w, t1.w);
            }
            acc0.x = fmaf(a0[i0].x, t0.x, acc0.x);
            acc0.y = fmaf(a0[i0].y, t0.y, acc0.y);
            acc0.z = fmaf(a0[i0].z, t0.z, acc0.z);
            acc0.w = fmaf(a0[i0].w, t0.w, acc0.w);
            acc1.x = fmaf(a1[i0].x, t1.x, acc1.x);
            acc1.y = fmaf(a1[i0].y, t1.y, acc1.y);
            acc1.z = fmaf(a1[i0].z, t1.z, acc1.z);
            acc1.w = fmaf(a1[i0].w, t1.w, acc1.w);
        }
        out[base0 + i2 * (U / 4)] = acc0;
        if (has2) out[base1 + i2 * (U / 4)] = acc1;
    }
}

extern "C" void kernel_launch(void* const* d_in, const int* in_sizes, int n_in,
                              void* d_out, int out_size) {
    const float4* x0    = (const float4*)d_in[0];
    const float4* x1    = (const float4*)d_in[1];
    const float*  coeff = (const float*)d_in[2];
    const int*    idx   = (const int*)d_in[3];
    float4*       out   = (float4*)d_out;

    int nrows = in_sizes[0] / (NSEG * U);   // 100000

    int npairs = (nrows + 1) / 2;            // one warp per 2 rows
    int total_threads = npairs * 32;
    int block = 256;
    int grid  = (total_threads + block - 1) / block;
    tp_uniform_fused_kernel<<<grid, block>>>(x0, x1, coeff, idx, out, nrows);
}

// round 8
// speedup vs baseline: 1.0240x; 1.0240x over previous
#include <cuda_runtime.h>

// TensorProductUniform3x1d:
//   B=100000, NSEG=4, U=128, NPATH=20
//   out[b, i2, :] += c[p] * x0[b, i0[p], :] * x1[b, i1[p], :]
//
// R8: persistent grid-stride kernel — exactly one wave (148 SMs x 4 CTAs),
// each warp loops over rows with stride = total warps. Removes ~20 wave
// transitions and lets next-iteration loads overlap current stores.
// Per-row computation identical to the measured-best R2 config:
// float4 width, fused shared-memory W build, default cache policy.

#define NSEG 4
#define U 128
#define NPATH 20

#define NUM_SMS 148
#define CTAS_PER_SM 4

__global__ __launch_bounds__(256, CTAS_PER_SM)
void tp_uniform_persistent_kernel(const float4* __restrict__ x0,
                                  const float4* __restrict__ x1,
                                  const float*  __restrict__ coeff,
                                  const int*    __restrict__ idx,
                                  float4* __restrict__ out,
                                  int nrows) {
    __shared__ float sW[NSEG * NSEG * NSEG];

    // Build W[i2][i0][i1] = sum_p coeff[p] * [idx[p]==(i0,i1,i2)]
    int t = threadIdx.x;
    if (t < NSEG * NSEG * NSEG) {
        int i2 = t >> 4;
        int i0 = (t >> 2) & 3;
        int i1 = t & 3;
        float w = 0.0f;
        #pragma unroll
        for (int p = 0; p < NPATH; p++) {
            int p0 = __ldg(&idx[3 * p + 0]);
            int p1 = __ldg(&idx[3 * p + 1]);
            int p2 = __ldg(&idx[3 * p + 2]);
            if (p0 == i0 && p1 == i1 && p2 == i2) w += __ldg(&coeff[p]);
        }
        sW[t] = w;
    }
    __syncthreads();

    int gid    = blockIdx.x * blockDim.x + threadIdx.x;
    int warp0  = gid >> 5;                       // starting row for this warp
    int lane   = gid & 31;
    int nwarps = (gridDim.x * blockDim.x) >> 5;  // total warps = row stride

    const int RS = NSEG * U / 4;                 // 128 float4 per row

    for (int row = warp0; row < nrows; row += nwarps) {
        size_t base = (size_t)row * RS + lane;

        // Front-batch all 8 loads (default cache policy — measured best).
        float4 a[NSEG], b[NSEG];
        #pragma unroll
        for (int s = 0; s < NSEG; s++) a[s] = __ldg(&x0[base + s * (U / 4)]);
        #pragma unroll
        for (int s = 0; s < NSEG; s++) b[s] = __ldg(&x1[base + s * (U / 4)]);

        // out[i2] = sum_{i0} a[i0] * ( sum_{i1} W[i2][i0][i1] * b[i1] )
        #pragma unroll
        for (int i2 = 0; i2 < NSEG; i2++) {
            float4 acc = make_float4(0.f, 0.f, 0.f, 0.f);
            #pragma unroll
            for (int i0 = 0; i0 < NSEG; i0++) {
                float4 tt = make_float4(0.f, 0.f, 0.f, 0.f);
                #pragma unroll
                for (int i1 = 0; i1 < NSEG; i1++) {
                    float w = sW[(i2 * NSEG + i0) * NSEG + i1];
                    tt.x = fmaf(w, b[i1].x, tt.x);
                    tt.y = fmaf(w, b[i1].y, tt.y);
                    tt.z = fmaf(w, b[i1].z, tt.z);
                    tt.w = fmaf(w, b[i1].w, tt.w);
                }
                acc.x = fmaf(a[i0].x, tt.x, acc.x);
                acc.y = fmaf(a[i0].y, tt.y, acc.y);
                acc.z = fmaf(a[i0].z, tt.z, acc.z);
                acc.w = fmaf(a[i0].w, tt.w, acc.w);
            }
            out[base + i2 * (U / 4)] = acc;
        }
    }
}

extern "C" void kernel_launch(void* const* d_in, const int* in_sizes, int n_in,
                              void* d_out, int out_size) {
    const float4* x0    = (const float4*)d_in[0];
    const float4* x1    = (const float4*)d_in[1];
    const float*  coeff = (const float*)d_in[2];
    const int*    idx   = (const int*)d_in[3];
    float4*       out   = (float4*)d_out;

    int nrows = in_sizes[0] / (NSEG * U);   // 100000

    int grid = NUM_SMS * CTAS_PER_SM;       // one resident wave
    tp_uniform_persistent_kernel<<<grid, 256>>>(x0, x1, coeff, idx, out, nrows);
}

// round 9
// speedup vs baseline: 1.1578x; 1.1306x over previous
#include <cuda_runtime.h>

// TensorProductUniform3x1d:
//   B=100000, NSEG=4, U=128, NPATH=20
//   out[b, i2, :] += c[p] * x0[b, i0[p], :] * x1[b, i1[p], :]
//
// R9: measured-best R2 configuration (float4, one warp per row, linear CTA
// order, default cache policy, fused shared W build) with 512-thread blocks:
// same 32 warps/SM occupancy, but half the CTAs -> half the redundant W
// builds and a 32KB contiguous span per scheduling unit.

#define NSEG 4
#define U 128
#define NPATH 20

__global__ __launch_bounds__(512, 2)
void tp_uniform_fused_kernel(const float4* __restrict__ x0,
                             const float4* __restrict__ x1,
                             const float*  __restrict__ coeff,
                             const int*    __restrict__ idx,
                             float4* __restrict__ out,
                             int nrows) {
    __shared__ float sW[NSEG * NSEG * NSEG];

    // Build W[i2][i0][i1] = sum_p coeff[p] * [idx[p]==(i0,i1,i2)]
    int t = threadIdx.x;
    if (t < NSEG * NSEG * NSEG) {
        int i2 = t >> 4;
        int i0 = (t >> 2) & 3;
        int i1 = t & 3;
        float w = 0.0f;
        #pragma unroll
        for (int p = 0; p < NPATH; p++) {
            int p0 = __ldg(&idx[3 * p + 0]);
            int p1 = __ldg(&idx[3 * p + 1]);
            int p2 = __ldg(&idx[3 * p + 2]);
            if (p0 == i0 && p1 == i1 && p2 == i2) w += __ldg(&coeff[p]);
        }
        sW[t] = w;
    }
    __syncthreads();

    int gid  = blockIdx.x * blockDim.x + threadIdx.x;
    int row  = gid >> 5;
    int lane = gid & 31;
    if (row >= nrows) return;

    size_t base = (size_t)row * (NSEG * U / 4) + lane;  // float4 units

    // Front-batch all 8 loads (default cache policy — measured best).
    float4 a[NSEG], b[NSEG];
    #pragma unroll
    for (int s = 0; s < NSEG; s++) a[s] = __ldg(&x0[base + s * (U / 4)]);
    #pragma unroll
    for (int s = 0; s < NSEG; s++) b[s] = __ldg(&x1[base + s * (U / 4)]);

    // out[i2] = sum_{i0} a[i0] * ( sum_{i1} W[i2][i0][i1] * b[i1] )
    #pragma unroll
    for (int i2 = 0; i2 < NSEG; i2++) {
        float4 acc = make_float4(0.f, 0.f, 0.f, 0.f);
        #pragma unroll
        for (int i0 = 0; i0 < NSEG; i0++) {
            float4 tt = make_float4(0.f, 0.f, 0.f, 0.f);
            #pragma unroll
            for (int i1 = 0; i1 < NSEG; i1++) {
                float w = sW[(i2 * NSEG + i0) * NSEG + i1];
                tt.x = fmaf(w, b[i1].x, tt.x);
                tt.y = fmaf(w, b[i1].y, tt.y);
                tt.z = fmaf(w, b[i1].z, tt.z);
                tt.w = fmaf(w, b[i1].w, tt.w);
            }
            acc.x = fmaf(a[i0].x, tt.x, acc.x);
            acc.y = fmaf(a[i0].y, tt.y, acc.y);
            acc.z = fmaf(a[i0].z, tt.z, acc.z);
            acc.w = fmaf(a[i0].w, tt.w, acc.w);
        }
        out[base + i2 * (U / 4)] = acc;
    }
}

extern "C" void kernel_launch(void* const* d_in, const int* in_sizes, int n_in,
                              void* d_out, int out_size) {
    const float4* x0    = (const float4*)d_in[0];
    const float4* x1    = (const float4*)d_in[1];
    const float*  coeff = (const float*)d_in[2];
    const int*    idx   = (const int*)d_in[3];
    float4*       out   = (float4*)d_out;

    int nrows = in_sizes[0] / (NSEG * U);   // 100000

    int total_threads = nrows * 32;         // one warp per row
    int block = 512;
    int grid  = (total_threads + block - 1) / block;
    tp_uniform_fused_kernel<<<grid, block>>>(x0, x1, coeff, idx, out, nrows);
}